// round 1
// baseline (speedup 1.0000x reference)
#include <cuda_runtime.h>
#include <cuda_bf16.h>

#define N_NODES 100000
#define N_EDGES 1600000
#define F 128

// ---------------- scratch (static __device__, no allocation) ----------------
__device__ float g_agg1[(size_t)N_NODES * F];   // 51.2 MB layer-1 aggregation
__device__ float g_y[(size_t)N_NODES * 2];      // per-node 2-wide layer-2 input
__device__ float g_rs_out[N_NODES];
__device__ float g_rs_in[N_NODES];
__device__ float g_deg_out[N_NODES];
__device__ float g_deg_in[N_NODES];

// ---------------- reduction helpers (no-return atomics -> REDG) -------------
__device__ __forceinline__ void red_add1(float* p, float v) {
    asm volatile("red.global.add.f32 [%0], %1;" :: "l"(p), "f"(v) : "memory");
}
__device__ __forceinline__ void red_add2(float* p, float a, float b) {
    asm volatile("red.global.add.v2.f32 [%0], {%1,%2};"
                 :: "l"(p), "f"(a), "f"(b) : "memory");
}
__device__ __forceinline__ void red_add4(float* p, float4 v) {
    asm volatile("red.global.add.v4.f32 [%0], {%1,%2,%3,%4};"
                 :: "l"(p), "f"(v.x), "f"(v.y), "f"(v.z), "f"(v.w) : "memory");
}

// ---------------- zeroing ----------------------------------------------------
__global__ void k_zero_agg() {
    int i = blockIdx.x * blockDim.x + threadIdx.x;         // n4 = N_NODES*32
    if (i < N_NODES * 32) ((float4*)g_agg1)[i] = make_float4(0.f, 0.f, 0.f, 0.f);
}
__global__ void k_zero_deg() {
    int i = blockIdx.x * blockDim.x + threadIdx.x;
    if (i < N_NODES) { g_deg_out[i] = 0.f; g_deg_in[i] = 0.f; }
}
__global__ void k_zero_out(float* __restrict__ out) {
    int i = blockIdx.x * blockDim.x + threadIdx.x;
    if (i < N_NODES) ((float2*)out)[i] = make_float2(0.f, 0.f);
}

// ---------------- degrees ----------------------------------------------------
__global__ void k_deg(const int* __restrict__ src, const int* __restrict__ dst) {
    int i = blockIdx.x * blockDim.x + threadIdx.x;
    if (i < N_EDGES) {
        red_add1(&g_deg_out[src[i]], 1.0f);
        red_add1(&g_deg_in[dst[i]], 1.0f);
    }
}
__global__ void k_rs() {
    int i = blockIdx.x * blockDim.x + threadIdx.x;
    if (i < N_NODES) {
        g_rs_out[i] = rsqrtf(fmaxf(g_deg_out[i], 1.0f));
        g_rs_in[i]  = rsqrtf(fmaxf(g_deg_in[i], 1.0f));
    }
}

// ---------------- layer-1 scatter: warp per edge -----------------------------
// agg1[dst] += in_feat[src] * rs_out[src]   (128 floats = 32 lanes x float4)
__global__ void __launch_bounds__(256) k_scatter1(const float4* __restrict__ x,
                                                  const int* __restrict__ src,
                                                  const int* __restrict__ dst) {
    int t = blockIdx.x * blockDim.x + threadIdx.x;
    int e = t >> 5, lane = t & 31;
    if (e >= N_EDGES) return;
    int s = src[e], d = dst[e];                // same-address broadcast loads
    float sc = g_rs_out[s];
    float4 v = x[s * 32 + lane];
    v.x *= sc; v.y *= sc; v.z *= sc; v.w *= sc;
    red_add4(&g_agg1[(size_t)d * 128 + lane * 4], v);
}

// ---------------- fused node kernel ------------------------------------------
// y[i] = ( relu( (agg1[i]*rs_in[i]) @ W1 + b1 ) @ W2 ) * rs_out[i]
// Block = 256 thr (8 warps), warp handles 4 nodes. Lane owns cols 4l..4l+3.
// Dynamic smem: W1 (64KB) + b1 (512B) + W2 (1KB).
__global__ void __launch_bounds__(256) k_node(const float* __restrict__ W1,
                                              const float* __restrict__ b1,
                                              const float* __restrict__ W2) {
    extern __shared__ float smem[];
    float4* Ws   = (float4*)smem;              // 4096 float4 = W1[k][c] row-major
    float4* b1s4 = (float4*)(smem + 16384);    // 32 float4
    float2* W2s  = (float2*)(smem + 16384 + 128); // 128 float2

    int tid = threadIdx.x;
    const float4* W14 = (const float4*)W1;
    #pragma unroll
    for (int i = 0; i < 16; i++) Ws[tid + i * 256] = W14[tid + i * 256];
    if (tid < 32)  b1s4[tid] = ((const float4*)b1)[tid];
    if (tid < 128) W2s[tid]  = ((const float2*)W2)[tid];
    __syncthreads();

    int warp = tid >> 5, lane = tid & 31;
    int i0 = blockIdx.x * 32 + warp * 4;       // 3125 blocks * 32 = 100000 exactly

    const float4* agg4 = (const float4*)g_agg1;
    float4 a[4];
    #pragma unroll
    for (int m = 0; m < 4; m++) {
        float ri = g_rs_in[i0 + m];
        float4 t = agg4[(i0 + m) * 32 + lane];
        a[m] = make_float4(t.x * ri, t.y * ri, t.z * ri, t.w * ri);
    }

    float4 acc[4];
    #pragma unroll
    for (int m = 0; m < 4; m++) acc[m] = b1s4[lane];

    #pragma unroll 8
    for (int sl = 0; sl < 32; ++sl) {
        #pragma unroll
        for (int j = 0; j < 4; j++) {
            int k = sl * 4 + j;
            float4 wv = Ws[k * 32 + lane];
            float x0, x1, x2, x3;
            if      (j == 0) { x0 = a[0].x; x1 = a[1].x; x2 = a[2].x; x3 = a[3].x; }
            else if (j == 1) { x0 = a[0].y; x1 = a[1].y; x2 = a[2].y; x3 = a[3].y; }
            else if (j == 2) { x0 = a[0].z; x1 = a[1].z; x2 = a[2].z; x3 = a[3].z; }
            else             { x0 = a[0].w; x1 = a[1].w; x2 = a[2].w; x3 = a[3].w; }
            x0 = __shfl_sync(0xffffffffu, x0, sl);
            x1 = __shfl_sync(0xffffffffu, x1, sl);
            x2 = __shfl_sync(0xffffffffu, x2, sl);
            x3 = __shfl_sync(0xffffffffu, x3, sl);
            acc[0].x += x0 * wv.x; acc[0].y += x0 * wv.y; acc[0].z += x0 * wv.z; acc[0].w += x0 * wv.w;
            acc[1].x += x1 * wv.x; acc[1].y += x1 * wv.y; acc[1].z += x1 * wv.z; acc[1].w += x1 * wv.w;
            acc[2].x += x2 * wv.x; acc[2].y += x2 * wv.y; acc[2].z += x2 * wv.z; acc[2].w += x2 * wv.w;
            acc[3].x += x3 * wv.x; acc[3].y += x3 * wv.y; acc[3].z += x3 * wv.z; acc[3].w += x3 * wv.w;
        }
    }

    // relu + W2 (128x2) projection, then warp-reduce
    float2 w0 = W2s[4 * lane + 0], w1 = W2s[4 * lane + 1];
    float2 w2 = W2s[4 * lane + 2], w3 = W2s[4 * lane + 3];
    float p0[4], p1[4];
    #pragma unroll
    for (int m = 0; m < 4; m++) {
        float h0 = fmaxf(acc[m].x, 0.f), h1 = fmaxf(acc[m].y, 0.f);
        float h2 = fmaxf(acc[m].z, 0.f), h3 = fmaxf(acc[m].w, 0.f);
        p0[m] = h0 * w0.x + h1 * w1.x + h2 * w2.x + h3 * w3.x;
        p1[m] = h0 * w0.y + h1 * w1.y + h2 * w2.y + h3 * w3.y;
    }
    #pragma unroll
    for (int off = 16; off; off >>= 1) {
        #pragma unroll
        for (int m = 0; m < 4; m++) {
            p0[m] += __shfl_xor_sync(0xffffffffu, p0[m], off);
            p1[m] += __shfl_xor_sync(0xffffffffu, p1[m], off);
        }
    }
    if (lane == 0) {
        float2* y2 = (float2*)g_y;
        #pragma unroll
        for (int m = 0; m < 4; m++) {
            float ro = g_rs_out[i0 + m];
            y2[i0 + m] = make_float2(p0[m] * ro, p1[m] * ro);
        }
    }
}

// ---------------- layer-2 scatter: thread per edge ---------------------------
__global__ void k_scatter2(const int* __restrict__ src, const int* __restrict__ dst,
                           float* __restrict__ out) {
    int e = blockIdx.x * blockDim.x + threadIdx.x;
    if (e < N_EDGES) {
        int s = src[e], d = dst[e];
        float2 v = ((const float2*)g_y)[s];
        red_add2(&out[d * 2], v.x, v.y);
    }
}

// ---------------- finalize: out = out * rs_in + b2 ---------------------------
__global__ void k_final(float* __restrict__ out, const float* __restrict__ b2) {
    int i = blockIdx.x * blockDim.x + threadIdx.x;
    if (i < N_NODES) {
        float ri = g_rs_in[i];
        float2 v = ((float2*)out)[i];
        ((float2*)out)[i] = make_float2(v.x * ri + b2[0], v.y * ri + b2[1]);
    }
}

// ---------------- launch ------------------------------------------------------
extern "C" void kernel_launch(void* const* d_in, const int* in_sizes, int n_in,
                              void* d_out, int out_size) {
    const float* in_feat = (const float*)d_in[0];
    const int*   src     = (const int*)d_in[1];
    const int*   dst     = (const int*)d_in[2];
    const float* W1      = (const float*)d_in[3];
    const float* b1      = (const float*)d_in[4];
    const float* W2      = (const float*)d_in[5];
    const float* b2      = (const float*)d_in[6];
    float*       out     = (float*)d_out;

    const int T = 256;
    const int SMEM_NODE = (16384 + 128 + 256) * (int)sizeof(float); // 67072 B
    cudaFuncSetAttribute(k_node, cudaFuncAttributeMaxDynamicSharedMemorySize, SMEM_NODE);

    k_zero_agg<<<(N_NODES * 32 + T - 1) / T, T>>>();
    k_zero_deg<<<(N_NODES + T - 1) / T, T>>>();
    k_zero_out<<<(N_NODES + T - 1) / T, T>>>(out);
    k_deg<<<(N_EDGES + T - 1) / T, T>>>(src, dst);
    k_rs<<<(N_NODES + T - 1) / T, T>>>();
    {
        long long threads = (long long)N_EDGES * 32;
        k_scatter1<<<(int)((threads + T - 1) / T), T>>>((const float4*)in_feat, src, dst);
    }
    k_node<<<N_NODES / 32, T, SMEM_NODE>>>(W1, b1, W2);
    k_scatter2<<<(N_EDGES + T - 1) / T, T>>>(src, dst, out);
    k_final<<<(N_NODES + T - 1) / T, T>>>(out, b2);
}

// round 2
// speedup vs baseline: 1.6244x; 1.6244x over previous
#include <cuda_runtime.h>
#include <cuda_bf16.h>

#define N_NODES 100000
#define N_EDGES 1600000
#define F 128
#define NB_SCAN 98            // ceil(100000/1024)

// ---------------- scratch (static __device__, no allocation) ----------------
__device__ int   g_deg_out_i[N_NODES];
__device__ int   g_deg_in_i[N_NODES];
__device__ float g_rs_out[N_NODES];
__device__ float g_rs_in[N_NODES];
__device__ int   g_rowp[N_NODES + 1];     // CSR row pointers (by dst)
__device__ int   g_cursor[N_NODES];       // fill cursors
__device__ int   g_csr[N_EDGES];          // src indices grouped by dst
__device__ int   g_bsum[NB_SCAN];
__device__ int   g_boff[NB_SCAN];
__device__ float g_y[(size_t)N_NODES * 2];

// ---------------- zero counters ----------------------------------------------
__global__ void k_zero() {
    int i = blockIdx.x * blockDim.x + threadIdx.x;
    if (i < N_NODES) { g_deg_out_i[i] = 0; g_deg_in_i[i] = 0; }
}

// ---------------- degrees (int histogram, RED to L2) -------------------------
__global__ void k_deg(const int* __restrict__ src, const int* __restrict__ dst) {
    int i = blockIdx.x * blockDim.x + threadIdx.x;
    if (i < N_EDGES) {
        atomicAdd(&g_deg_out_i[src[i]], 1);
        atomicAdd(&g_deg_in_i[dst[i]], 1);
    }
}

__global__ void k_rs() {
    int i = blockIdx.x * blockDim.x + threadIdx.x;
    if (i < N_NODES) {
        g_rs_out[i] = rsqrtf(fmaxf((float)g_deg_out_i[i], 1.0f));
        g_rs_in[i]  = rsqrtf(fmaxf((float)g_deg_in_i[i],  1.0f));
    }
}

// ---------------- exclusive scan of deg_in -> row_ptr ------------------------
__global__ void k_scan_block() {
    __shared__ int s[1024];
    int tid = threadIdx.x;
    int gid = blockIdx.x * 1024 + tid;
    int v = (gid < N_NODES) ? g_deg_in_i[gid] : 0;
    s[tid] = v; __syncthreads();
    #pragma unroll
    for (int off = 1; off < 1024; off <<= 1) {
        int t = (tid >= off) ? s[tid - off] : 0;
        __syncthreads();
        s[tid] += t;
        __syncthreads();
    }
    if (gid < N_NODES) g_rowp[gid + 1] = s[tid];   // inclusive, pre-offset
    if (tid == 1023) g_bsum[blockIdx.x] = s[1023];
}

__global__ void k_scan_sums() {
    __shared__ int s[128];
    int tid = threadIdx.x;
    int v = (tid < NB_SCAN) ? g_bsum[tid] : 0;
    s[tid] = v; __syncthreads();
    #pragma unroll
    for (int off = 1; off < 128; off <<= 1) {
        int t = (tid >= off) ? s[tid - off] : 0;
        __syncthreads();
        s[tid] += t;
        __syncthreads();
    }
    if (tid < NB_SCAN) g_boff[tid] = s[tid] - v;   // exclusive
}

__global__ void k_scan_add() {
    int gid = blockIdx.x * blockDim.x + threadIdx.x;
    if (gid < N_NODES) {
        int v = g_rowp[gid + 1] + g_boff[gid >> 10];
        g_rowp[gid + 1] = v;
        if (gid + 1 < N_NODES) g_cursor[gid + 1] = v;
        if (gid == 0) { g_rowp[0] = 0; g_cursor[0] = 0; }
    }
}

// ---------------- CSR bucket fill --------------------------------------------
__global__ void k_fill(const int* __restrict__ src, const int* __restrict__ dst) {
    int e = blockIdx.x * blockDim.x + threadIdx.x;
    if (e < N_EDGES) {
        int d = dst[e];
        int p = atomicAdd(&g_cursor[d], 1);
        g_csr[p] = src[e];
    }
}

// ---------------- fused layer-1: gather + W1 GEMM + relu + W2 -> y -----------
// Warp handles 4 nodes: a[m] = rs_in * sum_{e in in(m)} x[src_e]*rs_out[src_e]
// then GEMM via shfl, relu, 128x2 projection, *rs_out -> g_y.
__global__ void __launch_bounds__(256) k_fused1(const float4* __restrict__ x4,
                                                const float* __restrict__ W1,
                                                const float* __restrict__ b1,
                                                const float* __restrict__ W2) {
    extern __shared__ float smem[];
    float4* Ws   = (float4*)smem;                  // 4096 float4: W1[k][c]
    float4* b1s4 = (float4*)(smem + 16384);        // 32 float4
    float2* W2s  = (float2*)(smem + 16384 + 128);  // 128 float2

    int tid = threadIdx.x;
    const float4* W14 = (const float4*)W1;
    #pragma unroll
    for (int i = 0; i < 16; i++) Ws[tid + i * 256] = W14[tid + i * 256];
    if (tid < 32)  b1s4[tid] = ((const float4*)b1)[tid];
    if (tid < 128) W2s[tid]  = ((const float2*)W2)[tid];
    __syncthreads();

    int warp = tid >> 5, lane = tid & 31;
    int i0 = blockIdx.x * 32 + warp * 4;           // 3125 * 32 = 100000

    float4 a[4];
    #pragma unroll
    for (int m = 0; m < 4; m++) {
        int node = i0 + m;
        int beg = __ldg(&g_rowp[node]), end = __ldg(&g_rowp[node + 1]);
        float4 acc = make_float4(0.f, 0.f, 0.f, 0.f);
        int e = beg;
        for (; e + 2 <= end; e += 2) {
            int s0 = __ldg(&g_csr[e]), s1 = __ldg(&g_csr[e + 1]);
            float c0 = __ldg(&g_rs_out[s0]), c1 = __ldg(&g_rs_out[s1]);
            float4 v0 = x4[s0 * 32 + lane];
            float4 v1 = x4[s1 * 32 + lane];
            acc.x += v0.x * c0 + v1.x * c1;
            acc.y += v0.y * c0 + v1.y * c1;
            acc.z += v0.z * c0 + v1.z * c1;
            acc.w += v0.w * c0 + v1.w * c1;
        }
        if (e < end) {
            int s0 = __ldg(&g_csr[e]);
            float c0 = __ldg(&g_rs_out[s0]);
            float4 v0 = x4[s0 * 32 + lane];
            acc.x += v0.x * c0; acc.y += v0.y * c0;
            acc.z += v0.z * c0; acc.w += v0.w * c0;
        }
        float ri = g_rs_in[node];
        a[m] = make_float4(acc.x * ri, acc.y * ri, acc.z * ri, acc.w * ri);
    }

    float4 acc[4];
    #pragma unroll
    for (int m = 0; m < 4; m++) acc[m] = b1s4[lane];

    #pragma unroll 8
    for (int sl = 0; sl < 32; ++sl) {
        #pragma unroll
        for (int j = 0; j < 4; j++) {
            int k = sl * 4 + j;
            float4 wv = Ws[k * 32 + lane];
            float x0, x1, x2, x3;
            if      (j == 0) { x0 = a[0].x; x1 = a[1].x; x2 = a[2].x; x3 = a[3].x; }
            else if (j == 1) { x0 = a[0].y; x1 = a[1].y; x2 = a[2].y; x3 = a[3].y; }
            else if (j == 2) { x0 = a[0].z; x1 = a[1].z; x2 = a[2].z; x3 = a[3].z; }
            else             { x0 = a[0].w; x1 = a[1].w; x2 = a[2].w; x3 = a[3].w; }
            x0 = __shfl_sync(0xffffffffu, x0, sl);
            x1 = __shfl_sync(0xffffffffu, x1, sl);
            x2 = __shfl_sync(0xffffffffu, x2, sl);
            x3 = __shfl_sync(0xffffffffu, x3, sl);
            acc[0].x += x0 * wv.x; acc[0].y += x0 * wv.y; acc[0].z += x0 * wv.z; acc[0].w += x0 * wv.w;
            acc[1].x += x1 * wv.x; acc[1].y += x1 * wv.y; acc[1].z += x1 * wv.z; acc[1].w += x1 * wv.w;
            acc[2].x += x2 * wv.x; acc[2].y += x2 * wv.y; acc[2].z += x2 * wv.z; acc[2].w += x2 * wv.w;
            acc[3].x += x3 * wv.x; acc[3].y += x3 * wv.y; acc[3].z += x3 * wv.z; acc[3].w += x3 * wv.w;
        }
    }

    float2 w0 = W2s[4 * lane + 0], w1 = W2s[4 * lane + 1];
    float2 w2 = W2s[4 * lane + 2], w3 = W2s[4 * lane + 3];
    float p0[4], p1[4];
    #pragma unroll
    for (int m = 0; m < 4; m++) {
        float h0 = fmaxf(acc[m].x, 0.f), h1 = fmaxf(acc[m].y, 0.f);
        float h2 = fmaxf(acc[m].z, 0.f), h3 = fmaxf(acc[m].w, 0.f);
        p0[m] = h0 * w0.x + h1 * w1.x + h2 * w2.x + h3 * w3.x;
        p1[m] = h0 * w0.y + h1 * w1.y + h2 * w2.y + h3 * w3.y;
    }
    #pragma unroll
    for (int off = 16; off; off >>= 1) {
        #pragma unroll
        for (int m = 0; m < 4; m++) {
            p0[m] += __shfl_xor_sync(0xffffffffu, p0[m], off);
            p1[m] += __shfl_xor_sync(0xffffffffu, p1[m], off);
        }
    }
    if (lane == 0) {
        float2* y2 = (float2*)g_y;
        #pragma unroll
        for (int m = 0; m < 4; m++) {
            float ro = g_rs_out[i0 + m];
            y2[i0 + m] = make_float2(p0[m] * ro, p1[m] * ro);
        }
    }
}

// ---------------- layer-2: CSR gather of y + finalize ------------------------
__global__ void k_out(float* __restrict__ out, const float* __restrict__ b2) {
    int i = blockIdx.x * blockDim.x + threadIdx.x;
    if (i >= N_NODES) return;
    int beg = __ldg(&g_rowp[i]), end = __ldg(&g_rowp[i + 1]);
    const float2* y2 = (const float2*)g_y;
    float s0 = 0.f, s1 = 0.f;
    int e = beg;
    for (; e + 2 <= end; e += 2) {
        int a = __ldg(&g_csr[e]), b = __ldg(&g_csr[e + 1]);
        float2 va = y2[a], vb = y2[b];
        s0 += va.x + vb.x;
        s1 += va.y + vb.y;
    }
    if (e < end) {
        float2 va = y2[__ldg(&g_csr[e])];
        s0 += va.x; s1 += va.y;
    }
    float ri = g_rs_in[i];
    ((float2*)out)[i] = make_float2(s0 * ri + __ldg(&b2[0]),
                                    s1 * ri + __ldg(&b2[1]));
}

// ---------------- launch ------------------------------------------------------
extern "C" void kernel_launch(void* const* d_in, const int* in_sizes, int n_in,
                              void* d_out, int out_size) {
    const float* in_feat = (const float*)d_in[0];
    const int*   src     = (const int*)d_in[1];
    const int*   dst     = (const int*)d_in[2];
    const float* W1      = (const float*)d_in[3];
    const float* b1      = (const float*)d_in[4];
    const float* W2      = (const float*)d_in[5];
    const float* b2      = (const float*)d_in[6];
    float*       out     = (float*)d_out;

    const int T = 256;
    const int SMEM_NODE = (16384 + 128 + 256) * (int)sizeof(float); // 67072 B
    cudaFuncSetAttribute(k_fused1, cudaFuncAttributeMaxDynamicSharedMemorySize, SMEM_NODE);

    k_zero<<<(N_NODES + T - 1) / T, T>>>();
    k_deg<<<(N_EDGES + T - 1) / T, T>>>(src, dst);
    k_rs<<<(N_NODES + T - 1) / T, T>>>();
    k_scan_block<<<NB_SCAN, 1024>>>();
    k_scan_sums<<<1, 128>>>();
    k_scan_add<<<(N_NODES + T - 1) / T, T>>>();
    k_fill<<<(N_EDGES + T - 1) / T, T>>>(src, dst);
    k_fused1<<<N_NODES / 32, T, SMEM_NODE>>>((const float4*)in_feat, W1, b1, W2);
    k_out<<<(N_NODES + T - 1) / T, T>>>(out, b2);
}